// round 2
// baseline (speedup 1.0000x reference)
#include <cuda_runtime.h>
#include <cuda_bf16.h>
#include <cstdint>

// Problem constants
#define B     16
#define CIN   256
#define COUT  256
#define Hdim  64
#define Wdim  64
#define STY   512
#define CIC   8          // ci chunk per smem stage

// Scratch (allocation-free rule: __device__ globals)
__device__ float g_s[B * CIN];                                   // style scales
__device__ float g_wgt[(size_t)B * CIN * 9 * COUT];              // [b][ci][tap][co], co fastest

// packed f32x2 fma: d = a*b + c lane-wise on two fp32
__device__ __forceinline__ unsigned long long fma2(unsigned long long a,
                                                   unsigned long long b,
                                                   unsigned long long c) {
    unsigned long long d;
    asm("fma.rn.f32x2 %0, %1, %2, %3;" : "=l"(d) : "l"(a), "l"(b), "l"(c));
    return d;
}

// ---------------------------------------------------------------------------
// Kernel 1: s[b][ci] = dot(w_style[b,:], aff_w[ci,:]) + aff_b[ci] + 1
// ---------------------------------------------------------------------------
__global__ void style_kernel(const float* __restrict__ w_style,
                             const float* __restrict__ aff_w,
                             const float* __restrict__ aff_b) {
    int warp = blockIdx.x * (blockDim.x >> 5) + (threadIdx.x >> 5);
    int lane = threadIdx.x & 31;
    if (warp >= B * CIN) return;
    int b  = warp / CIN;
    int ci = warp % CIN;
    const float4* ws = reinterpret_cast<const float4*>(w_style + (size_t)b * STY);
    const float4* aw = reinterpret_cast<const float4*>(aff_w  + (size_t)ci * STY);
    float sum = 0.f;
    #pragma unroll
    for (int j = lane; j < STY / 4; j += 32) {
        float4 a = ws[j], c = aw[j];
        sum += a.x * c.x + a.y * c.y + a.z * c.z + a.w * c.w;
    }
    #pragma unroll
    for (int o = 16; o; o >>= 1) sum += __shfl_xor_sync(0xffffffffu, sum, o);
    if (lane == 0) g_s[b * CIN + ci] = sum + aff_b[ci] + 1.0f;
}

// ---------------------------------------------------------------------------
// Kernel 2: modulate + demodulate -> g_wgt [b][ci][tap][co]
// ---------------------------------------------------------------------------
__global__ void modulate_kernel(const float* __restrict__ Wf) {
    int co = blockIdx.x;
    int b  = blockIdx.y;
    int ci = threadIdx.x;

    float s = g_s[b * CIN + ci];
    const float* wp = Wf + ((size_t)co * CIN + ci) * 9;
    float m[9];
    float ss = 0.f;
    #pragma unroll
    for (int t = 0; t < 9; t++) {
        m[t] = wp[t] * s;
        ss += m[t] * m[t];
    }

    __shared__ float red[256];
    red[ci] = ss;
    __syncthreads();
    #pragma unroll
    for (int st = 128; st > 0; st >>= 1) {
        if (ci < st) red[ci] += red[ci + st];
        __syncthreads();
    }
    float d = rsqrtf(red[0] + 1e-8f);

    float* op = g_wgt + ((size_t)(b * CIN + ci) * 9) * COUT + co;
    #pragma unroll
    for (int t = 0; t < 9; t++) op[(size_t)t * COUT] = m[t] * d;
}

// ---------------------------------------------------------------------------
// Kernel 3: direct conv with packed f32x2 FMA.
// block: 256 thr = 32 lanes x 8 warps. Tile: 16x16 px, 64 co.
// thread: 8 co x 4 pixel-PAIRS (8 px) of f32x2 accumulators.
// ---------------------------------------------------------------------------
__global__ void __launch_bounds__(256, 2)
conv_kernel(const float* __restrict__ x, float* __restrict__ out) {
    __shared__ __align__(16) float  xs[CIC][18][18];   // input tile + halo
    __shared__ __align__(16) float2 ws2[CIC][9][64];   // weights duplicated {w,w}

    const int tid = threadIdx.x;
    const int tx  = tid & 31;           // lane
    const int ty  = tid >> 5;           // warp -> co group

    const int tileY = (blockIdx.x >> 2) * 16;
    const int tileX = (blockIdx.x & 3) * 16;
    const int coBase = blockIdx.y * 64;
    const int b = blockIdx.z;

    // 4 contiguous pixel pairs per thread: pixel0 = 2*(tx + 32*pp)
    int base0[4];   // xs word offset (row*18 + col) at tap (0,0)
    int goff[4];    // global float offset of pixel0 in output plane
    #pragma unroll
    for (int pp = 0; pp < 4; pp++) {
        int pix = 2 * (tx + 32 * pp);
        int py = pix >> 4, px = pix & 15;      // px even
        base0[pp] = py * 18 + px;
        goff[pp]  = (tileY + py) * Wdim + (tileX + px);
    }

    unsigned long long acc[8][4];
    #pragma unroll
    for (int i = 0; i < 8; i++)
        #pragma unroll
        for (int pp = 0; pp < 4; pp++) acc[i][pp] = 0ull;

    const float* xb = x + (size_t)b * CIN * Hdim * Wdim;
    const float* wb = g_wgt + (size_t)b * CIN * 9 * COUT;

    for (int cc = 0; cc < CIN; cc += CIC) {
        // stage x tile (zero-padded halo)
        for (int idx = tid; idx < CIC * 18 * 18; idx += 256) {
            int ci  = idx / 324;
            int rem = idx - ci * 324;
            int r = rem / 18, c = rem - r * 18;
            int gy = tileY + r - 1, gx = tileX + c - 1;
            float v = 0.f;
            if ((unsigned)gy < (unsigned)Hdim && (unsigned)gx < (unsigned)Wdim)
                v = xb[(size_t)(cc + ci) * (Hdim * Wdim) + gy * Wdim + gx];
            xs[ci][r][c] = v;
        }
        // stage weights duplicated: ws2 = {w, w}
        for (int idx = tid; idx < CIC * 9 * 64; idx += 256) {
            int co  = idx & 63;
            int t2  = idx >> 6;
            int tap = t2 % 9;
            int ci  = t2 / 9;
            float v = wb[((size_t)(cc + ci) * 9 + tap) * COUT + coBase + co];
            ws2[ci][tap][co] = make_float2(v, v);
        }
        __syncthreads();

        #pragma unroll 1
        for (int ci = 0; ci < CIC; ci++) {
            const char* xbase = (const char*)&xs[ci][0][0];
            #pragma unroll
            for (int kh = 0; kh < 3; kh++) {
                // packed x pairs for the 3 kw taps of this row
                unsigned long long a0[4], a1[4], a2[4];
                #pragma unroll
                for (int pp = 0; pp < 4; pp++) {
                    int off = (base0[pp] + kh * 18) * 4;
                    a0[pp] = *(const unsigned long long*)(xbase + off);      // cols c,c+1
                    a2[pp] = *(const unsigned long long*)(xbase + off + 8);  // cols c+2,c+3
                    a1[pp] = (a0[pp] >> 32) | (a2[pp] << 32);                // cols c+1,c+2
                }
                #pragma unroll
                for (int kw = 0; kw < 3; kw++) {
                    const unsigned long long* xv = (kw == 0) ? a0 : (kw == 1) ? a1 : a2;
                    #pragma unroll
                    for (int i = 0; i < 8; i++) {
                        unsigned long long wv =
                            *(const unsigned long long*)&ws2[ci][kh * 3 + kw][ty + 8 * i];
                        #pragma unroll
                        for (int pp = 0; pp < 4; pp++)
                            acc[i][pp] = fma2(wv, xv[pp], acc[i][pp]);
                    }
                }
            }
        }
        __syncthreads();
    }

    float* ob = out + (size_t)b * COUT * Hdim * Wdim;
    #pragma unroll
    for (int i = 0; i < 8; i++) {
        int co = coBase + ty + 8 * i;
        float* orow = ob + (size_t)co * (Hdim * Wdim);
        #pragma unroll
        for (int pp = 0; pp < 4; pp++)
            *(unsigned long long*)&orow[goff[pp]] = acc[i][pp];
    }
}

// ---------------------------------------------------------------------------
extern "C" void kernel_launch(void* const* d_in, const int* in_sizes, int n_in,
                              void* d_out, int out_size) {
    const float* x       = (const float*)d_in[0];   // [16,256,64,64]
    const float* w_style = (const float*)d_in[1];   // [16,512]
    const float* Wf      = (const float*)d_in[2];   // [256,256,3,3]
    const float* aff_w   = (const float*)d_in[3];   // [256,512]
    const float* aff_b   = (const float*)d_in[4];   // [256]
    float* out = (float*)d_out;                     // [16,256,64,64]

    style_kernel<<<(B * CIN + 7) / 8, 256>>>(w_style, aff_w, aff_b);
    modulate_kernel<<<dim3(COUT, B), 256>>>(Wf);
    conv_kernel<<<dim3(16, 4, B), 256>>>(x, out);
}

// round 4
// speedup vs baseline: 2.4149x; 2.4149x over previous
#include <cuda_runtime.h>
#include <cuda_bf16.h>
#include <cstdint>

// ---------------- problem constants ----------------
#define B     16
#define CIN   256
#define COUT  256
#define HW    4096
#define STY   512
#define KTOT  2304          // 9 taps * 256 ci; k = tap*256 + ci
#define NSTG  72            // K stages of 32

// ---------------- scratch ----------------
__device__ float g_s[B * CIN];
__device__ __align__(16) __nv_bfloat16 g_wbh[(size_t)B * COUT * KTOT]; // [b][co][k]
__device__ __align__(16) __nv_bfloat16 g_wbl[(size_t)B * COUT * KTOT];
__device__ __align__(16) __nv_bfloat16 g_xh[(size_t)B * HW * CIN];     // [b][pix][ci]
__device__ __align__(16) __nv_bfloat16 g_xl[(size_t)B * HW * CIN];

// ---------------- helpers ----------------
__device__ __forceinline__ uint32_t smem_u32(const void* p) {
    uint32_t a;
    asm("{ .reg .u64 t; cvta.to.shared.u64 t, %1; cvt.u32.u64 %0, t; }" : "=r"(a) : "l"(p));
    return a;
}
__device__ __forceinline__ void ldsm_x4(uint32_t* r, uint32_t addr) {
    asm volatile("ldmatrix.sync.aligned.m8n8.x4.shared.b16 {%0,%1,%2,%3}, [%4];"
                 : "=r"(r[0]), "=r"(r[1]), "=r"(r[2]), "=r"(r[3]) : "r"(addr));
}
__device__ __forceinline__ void mma16816(float* c, const uint32_t* a,
                                         uint32_t b0, uint32_t b1) {
    asm volatile("mma.sync.aligned.m16n8k16.row.col.f32.bf16.bf16.f32 "
                 "{%0,%1,%2,%3}, {%4,%5,%6,%7}, {%8,%9}, {%0,%1,%2,%3};"
                 : "+f"(c[0]), "+f"(c[1]), "+f"(c[2]), "+f"(c[3])
                 : "r"(a[0]), "r"(a[1]), "r"(a[2]), "r"(a[3]), "r"(b0), "r"(b1));
}

// ---------------- smem layout: 80B-padded rows ----------------
// per buffer: AH 128x80, AL 128x80, BH 128x80, BL 128x80 = 40960B; 2 buffers
#define ROWB   80
#define PRECB  10240
#define BUFB   40960
#define SMEM_TOTAL (2 * BUFB)

// ---------------------------------------------------------------------------
__global__ void style_kernel(const float* __restrict__ w_style,
                             const float* __restrict__ aff_w,
                             const float* __restrict__ aff_b) {
    int warp = blockIdx.x * (blockDim.x >> 5) + (threadIdx.x >> 5);
    int lane = threadIdx.x & 31;
    if (warp >= B * CIN) return;
    int b  = warp / CIN;
    int ci = warp % CIN;
    const float4* ws = reinterpret_cast<const float4*>(w_style + (size_t)b * STY);
    const float4* aw = reinterpret_cast<const float4*>(aff_w  + (size_t)ci * STY);
    float sum = 0.f;
    #pragma unroll
    for (int j = lane; j < STY / 4; j += 32) {
        float4 a = ws[j], c = aw[j];
        sum += a.x * c.x + a.y * c.y + a.z * c.z + a.w * c.w;
    }
    #pragma unroll
    for (int o = 16; o; o >>= 1) sum += __shfl_xor_sync(0xffffffffu, sum, o);
    if (lane == 0) g_s[b * CIN + ci] = sum + aff_b[ci] + 1.0f;
}

// ---------------------------------------------------------------------------
// modulate + demodulate -> split-bf16 weights [b][co][k], k = tap*256+ci
// ---------------------------------------------------------------------------
__global__ void modulate_kernel(const float* __restrict__ Wf) {
    int co = blockIdx.x;
    int b  = blockIdx.y;
    int ci = threadIdx.x;

    float s = g_s[b * CIN + ci];
    const float* wp = Wf + ((size_t)co * CIN + ci) * 9;
    float m[9];
    float ss = 0.f;
    #pragma unroll
    for (int t = 0; t < 9; t++) { m[t] = wp[t] * s; ss += m[t] * m[t]; }

    __shared__ float red[256];
    red[ci] = ss;
    __syncthreads();
    #pragma unroll
    for (int st = 128; st > 0; st >>= 1) {
        if (ci < st) red[ci] += red[ci + st];
        __syncthreads();
    }
    float d = rsqrtf(red[0] + 1e-8f);

    size_t base = ((size_t)b * COUT + co) * KTOT;
    #pragma unroll
    for (int t = 0; t < 9; t++) {
        float w = m[t] * d;
        __nv_bfloat16 hi = __float2bfloat16_rn(w);
        __nv_bfloat16 lo = __float2bfloat16_rn(w - __bfloat162float(hi));
        g_wbh[base + t * 256 + ci] = hi;
        g_wbl[base + t * 256 + ci] = lo;
    }
}

// ---------------------------------------------------------------------------
// split/transpose x [b][ci][pix] fp32 -> [b][pix][ci] bf16 hi/lo
// ---------------------------------------------------------------------------
__global__ void split_kernel(const float* __restrict__ x) {
    __shared__ float t[32][33];
    int b  = blockIdx.z;
    int cb = blockIdx.y * 32;
    int pb = blockIdx.x * 32;
    int tx = threadIdx.x, ty = threadIdx.y;

    const float* xp = x + ((size_t)b * CIN + cb) * HW + pb;
    #pragma unroll
    for (int i = ty; i < 32; i += 8)
        t[i][tx] = xp[(size_t)i * HW + tx];
    __syncthreads();
    #pragma unroll
    for (int i = ty; i < 32; i += 8) {
        float v = t[tx][i];                      // ci = cb+tx, pix = pb+i
        __nv_bfloat16 h = __float2bfloat16_rn(v);
        size_t o = ((size_t)b * HW + pb + i) * CIN + cb + tx;
        g_xh[o] = h;
        g_xl[o] = __float2bfloat16_rn(v - __bfloat162float(h));
    }
}

// ---------------------------------------------------------------------------
// conv as implicit GEMM: D[pix,co] per b. CTA: M=128 px, N=128 co, 512 thr.
// ---------------------------------------------------------------------------
__global__ void __launch_bounds__(512, 1)
conv_kernel(float* __restrict__ out) {
    extern __shared__ __align__(16) char smem[];
    const uint32_t sbase = smem_u32(smem);

    const int tid   = threadIdx.x;
    const int wid   = tid >> 5;
    const int lane  = tid & 31;
    const int strip = blockIdx.x;          // 0..31 (128-px strips)
    const int coT   = blockIdx.y;          // 0..1
    const int b     = blockIdx.z;
    const int coBase = coT * 128;

    // staging role: threads 0-255 -> A rows, 256-511 -> B rows
    const bool isA = tid < 256;
    const int  srow = (tid & 255) >> 1;    // 0..127
    const int  shalf = tid & 1;            // 32B half of 64B row

    // ldmatrix lane addressing
    const int lr = (lane & 7) + (lane & 8);          // row within 16-group
    const int lc = ((lane >> 4) & 1) * 16;           // 16B col select
    const int wm = (wid & 3) * 32;                   // warp m origin
    const int wn = (wid >> 2) * 32;                  // warp n origin

    float acc[2][4][4];
    #pragma unroll
    for (int i = 0; i < 2; i++)
        #pragma unroll
        for (int j = 0; j < 4; j++)
            #pragma unroll
            for (int q = 0; q < 4; q++) acc[i][j][q] = 0.f;

    const __nv_bfloat16* xh = g_xh + (size_t)b * HW * CIN;
    const __nv_bfloat16* xl = g_xl + (size_t)b * HW * CIN;
    const __nv_bfloat16* wh = g_wbh + ((size_t)b * COUT + coBase) * KTOT;
    const __nv_bfloat16* wl = g_wbl + ((size_t)b * COUT + coBase) * KTOT;

    uint4 v[4];
    // ---- load stage s into v ----
    auto stage_load = [&](int s) {
        if (isA) {
            int tap = s >> 3, ci0 = (s & 7) << 5;
            int g = strip * 128 + srow;
            int y = (g >> 6) + tap / 3 - 1;
            int xx = (g & 63) + tap % 3 - 1;
            if ((unsigned)y < 64u && (unsigned)xx < 64u) {
                size_t e = ((size_t)(y * 64 + xx)) * CIN + ci0 + shalf * 16;
                v[0] = *(const uint4*)(xh + e);
                v[1] = *(const uint4*)(xh + e + 8);
                v[2] = *(const uint4*)(xl + e);
                v[3] = *(const uint4*)(xl + e + 8);
            } else {
                v[0] = v[1] = v[2] = v[3] = make_uint4(0, 0, 0, 0);
            }
        } else {
            size_t e = (size_t)srow * KTOT + s * 32 + shalf * 16;
            v[0] = *(const uint4*)(wh + e);
            v[1] = *(const uint4*)(wh + e + 8);
            v[2] = *(const uint4*)(wl + e);
            v[3] = *(const uint4*)(wl + e + 8);
        }
    };
    auto stage_sts = [&](int buf) {
        uint32_t o = buf * BUFB + (isA ? 0 : 2 * PRECB) + srow * ROWB + shalf * 32;
        *(uint4*)(smem + o)          = v[0];
        *(uint4*)(smem + o + 16)     = v[1];
        *(uint4*)(smem + o + PRECB)      = v[2];
        *(uint4*)(smem + o + PRECB + 16) = v[3];
    };

    stage_load(0);
    stage_sts(0);

    for (int s = 0; s < NSTG; s++) {
        if (s + 1 < NSTG) stage_load(s + 1);
        __syncthreads();

        const uint32_t Ab = sbase + (s & 1) * BUFB;
        const uint32_t Bb = Ab + 2 * PRECB;
        #pragma unroll
        for (int k16 = 0; k16 < 2; k16++) {
            const int kb = lc + k16 * 32;
            uint32_t ah[8], al[8], bh[8], bl[8];
            ldsm_x4(ah + 0, Ab + (wm + lr) * ROWB + kb);
            ldsm_x4(ah + 4, Ab + (wm + 16 + lr) * ROWB + kb);
            ldsm_x4(al + 0, Ab + PRECB + (wm + lr) * ROWB + kb);
            ldsm_x4(al + 4, Ab + PRECB + (wm + 16 + lr) * ROWB + kb);
            ldsm_x4(bh + 0, Bb + (wn + lr) * ROWB + kb);
            ldsm_x4(bh + 4, Bb + (wn + 16 + lr) * ROWB + kb);
            ldsm_x4(bl + 0, Bb + PRECB + (wn + lr) * ROWB + kb);
            ldsm_x4(bl + 4, Bb + PRECB + (wn + 16 + lr) * ROWB + kb);
            #pragma unroll
            for (int mh = 0; mh < 2; mh++)
                #pragma unroll
                for (int g = 0; g < 2; g++)
                    #pragma unroll
                    for (int j = 0; j < 2; j++) {
                        float* c = acc[mh][g * 2 + j];
                        mma16816(c, ah + mh * 4, bh[g * 4 + j], bh[g * 4 + j + 2]);
                        mma16816(c, ah + mh * 4, bl[g * 4 + j], bl[g * 4 + j + 2]);
                        mma16816(c, al + mh * 4, bh[g * 4 + j], bh[g * 4 + j + 2]);
                    }
        }
        __syncthreads();
        if (s + 1 < NSTG) stage_sts((s + 1) & 1);
    }

    // ---- epilogue ----
    float* ob = out + (size_t)b * COUT * HW;
    #pragma unroll
    for (int mh = 0; mh < 2; mh++)
        #pragma unroll
        for (int n8 = 0; n8 < 4; n8++) {
            int m  = strip * 128 + wm + mh * 16 + (lane >> 2);
            int co = coBase + wn + (n8 >> 1) * 16 + (n8 & 1) * 8 + (lane & 3) * 2;
            float* p = ob + (size_t)co * HW + m;
            const float* a = acc[mh][n8];
            p[0]      = a[0];
            p[HW]     = a[1];
            p[8]      = a[2];
            p[HW + 8] = a[3];
        }
}

// ---------------------------------------------------------------------------
extern "C" void kernel_launch(void* const* d_in, const int* in_sizes, int n_in,
                              void* d_out, int out_size) {
    const float* x       = (const float*)d_in[0];
    const float* w_style = (const float*)d_in[1];
    const float* Wf      = (const float*)d_in[2];
    const float* aff_w   = (const float*)d_in[3];
    const float* aff_b   = (const float*)d_in[4];
    float* out = (float*)d_out;

    style_kernel<<<(B * CIN + 7) / 8, 256>>>(w_style, aff_w, aff_b);
    modulate_kernel<<<dim3(COUT, B), 256>>>(Wf);
    split_kernel<<<dim3(HW / 32, CIN / 32, B), dim3(32, 8)>>>(x);

    static int configured = 0;
    cudaFuncSetAttribute(conv_kernel, cudaFuncAttributeMaxDynamicSharedMemorySize, SMEM_TOTAL);
    (void)configured;
    conv_kernel<<<dim3(32, 2, B), 512, SMEM_TOTAL>>>(out);
}